// round 1
// baseline (speedup 1.0000x reference)
#include <cuda_runtime.h>
#include <math.h>

// ---------------------------------------------------------------------------
// Problem dims
// ---------------------------------------------------------------------------
namespace {
constexpr int B_   = 16;
constexpr int L_   = 512;
constexpr int N_   = 321;
constexpr int MK_  = 4;
constexpr int D_   = 512;
constexpr int S_   = 16;
constexpr int DTR_ = 32;
constexpr int PRED_= 96;
constexpr int T_   = N_ + MK_;        // 325
constexpr int MROWS = B_ * T_;        // 5200
constexpr int XZW  = DTR_ + 2 * S_;   // 64
}

// ---------------------------------------------------------------------------
// Scratch (no allocations allowed -> __device__ globals)
// ---------------------------------------------------------------------------
__device__ float g_mean[B_ * N_];
__device__ float g_istd[B_ * N_];
__device__ float g_std [B_ * N_];
__device__ float g_tok  [(size_t)MROWS * L_];
__device__ float g_enc  [(size_t)MROWS * D_];
__device__ float g_xzf  [(size_t)MROWS * XZW];
__device__ float g_xzb  [(size_t)MROWS * XZW];
__device__ float g_dtf  [(size_t)MROWS * D_];
__device__ float g_dtb  [(size_t)MROWS * D_];
__device__ float g_ycat [(size_t)MROWS * 2 * D_];   // [yf | yb]
__device__ float g_fused[(size_t)MROWS * D_];
__device__ float g_hbuf [(size_t)MROWS * D_];
__device__ float g_hn   [(size_t)MROWS * D_];
__device__ float g_pre  [(size_t)MROWS * PRED_];

// ---------------------------------------------------------------------------
// 1) per-(b,n) mean / std over L
// ---------------------------------------------------------------------------
__global__ void stats_kernel(const float* __restrict__ x)
{
    // grid: (B_, ceil(N/32)), block: 256 = 32 n-lanes x 8 l-groups
    __shared__ float sh1[8][32];
    __shared__ float sh2[8][32];
    const int b  = blockIdx.x;
    const int tx = threadIdx.x & 31;
    const int lg = threadIdx.x >> 5;
    const int n  = blockIdx.y * 32 + tx;

    float s = 0.f, s2 = 0.f;
    if (n < N_) {
        #pragma unroll 4
        for (int l = lg; l < L_; l += 8) {
            float v = x[((size_t)b * L_ + l) * N_ + n];
            s  += v;
            s2 += v * v;
        }
    }
    sh1[lg][tx] = s;
    sh2[lg][tx] = s2;
    __syncthreads();
    if (lg == 0 && n < N_) {
        float S1 = 0.f, S2 = 0.f;
        #pragma unroll
        for (int r = 0; r < 8; r++) { S1 += sh1[r][tx]; S2 += sh2[r][tx]; }
        float mu  = S1 / (float)L_;
        float var = S2 / (float)L_ - mu * mu;
        float sd  = sqrtf(var + 1e-5f);
        g_mean[b * N_ + n] = mu;
        g_std [b * N_ + n] = sd;
        g_istd[b * N_ + n] = 1.f / sd;
    }
}

// ---------------------------------------------------------------------------
// 2) tok[b,t,l] = t<N ? (x_enc[b,l,t]-mean)/std : x_mark[b,l,t-N]
//    tiled transpose for coalescing both sides
// ---------------------------------------------------------------------------
__global__ void build_tok(const float* __restrict__ xe, const float* __restrict__ xm)
{
    __shared__ float tile[32][33];
    const int b  = blockIdx.z;
    const int tx = threadIdx.x, ty = threadIdx.y;
    const int t0 = blockIdx.x * 32;
    const int l0 = blockIdx.y * 32;

    #pragma unroll
    for (int j = 0; j < 4; j++) {
        int l = l0 + ty + 8 * j;      // always < 512
        int t = t0 + tx;
        float v = 0.f;
        if (t < T_) {
            if (t < N_) v = (xe[((size_t)b * L_ + l) * N_ + t] - g_mean[b * N_ + t]) * g_istd[b * N_ + t];
            else        v = xm[((size_t)b * L_ + l) * MK_ + (t - N_)];
        }
        tile[ty + 8 * j][tx] = v;
    }
    __syncthreads();
    #pragma unroll
    for (int j = 0; j < 4; j++) {
        int t = t0 + ty + 8 * j;
        int l = l0 + tx;
        if (t < T_) g_tok[((size_t)b * T_ + t) * L_ + l] = tile[tx][ty + 8 * j];
    }
}

// ---------------------------------------------------------------------------
// Tiled fp32 GEMM with fused epilogues.  C[M,N] = A[M,K] @ B[K,N] (+bias)(+epi)
// ---------------------------------------------------------------------------
constexpr int EPI_NONE = 0, EPI_SOFTPLUS = 1, EPI_SIGFUSE = 2, EPI_ADD = 3;

template<int BM, int BN, int BK, int TM, int TN, int EPI>
__global__ void __launch_bounds__((BM / TM) * (BN / TN))
gemm_k(const float* __restrict__ A, int lda,
       const float* __restrict__ Bm, int ldb,
       float* __restrict__ C, int ldc,
       int M, int Ncols, int K,
       const float* __restrict__ bias,
       const float* __restrict__ e1,
       const float* __restrict__ e2,
       int elds)
{
    constexpr int THREADS = (BM / TM) * (BN / TN);
    __shared__ float As[BK][BM];
    __shared__ float Bs[BK][BN];
    const int tid  = threadIdx.x;
    const int tcol = tid % (BN / TN);
    const int trow = tid / (BN / TN);
    const int rowBase = blockIdx.y * BM;
    const int colBase = blockIdx.x * BN;

    float acc[TM][TN];
    #pragma unroll
    for (int i = 0; i < TM; i++)
        #pragma unroll
        for (int j = 0; j < TN; j++) acc[i][j] = 0.f;

    for (int k0 = 0; k0 < K; k0 += BK) {
        for (int i = tid; i < BM * (BK / 4); i += THREADS) {
            int row = i / (BK / 4);
            int kq  = i % (BK / 4);
            float4 v = make_float4(0.f, 0.f, 0.f, 0.f);
            int gr = rowBase + row;
            if (gr < M) v = *reinterpret_cast<const float4*>(A + (size_t)gr * lda + k0 + kq * 4);
            As[kq * 4 + 0][row] = v.x;
            As[kq * 4 + 1][row] = v.y;
            As[kq * 4 + 2][row] = v.z;
            As[kq * 4 + 3][row] = v.w;
        }
        for (int i = tid; i < BK * (BN / 4); i += THREADS) {
            int kr = i / (BN / 4);
            int nq = i % (BN / 4);
            int gc = colBase + nq * 4;
            float4 v = make_float4(0.f, 0.f, 0.f, 0.f);
            if (gc < Ncols) v = *reinterpret_cast<const float4*>(Bm + (size_t)(k0 + kr) * ldb + gc);
            *reinterpret_cast<float4*>(&Bs[kr][nq * 4]) = v;
        }
        __syncthreads();
        #pragma unroll
        for (int k = 0; k < BK; k++) {
            float rm[TM], rn[TN];
            #pragma unroll
            for (int i = 0; i < TM; i++) rm[i] = As[k][trow * TM + i];
            #pragma unroll
            for (int j = 0; j < TN; j++) rn[j] = Bs[k][tcol * TN + j];
            #pragma unroll
            for (int i = 0; i < TM; i++)
                #pragma unroll
                for (int j = 0; j < TN; j++) acc[i][j] = fmaf(rm[i], rn[j], acc[i][j]);
        }
        __syncthreads();
    }

    #pragma unroll
    for (int i = 0; i < TM; i++) {
        int gr = rowBase + trow * TM + i;
        if (gr >= M) continue;
        #pragma unroll
        for (int j = 0; j < TN; j++) {
            int gc = colBase + tcol * TN + j;
            if (gc >= Ncols) continue;
            float v = acc[i][j];
            if (bias) v += bias[gc];
            if (EPI == EPI_SOFTPLUS) {
                v = (v > 15.f) ? v : log1pf(__expf(v));
            } else if (EPI == EPI_SIGFUSE) {
                float z = 1.f / (1.f + __expf(-v));
                size_t eidx = (size_t)gr * elds + gc;
                v = z * e1[eidx] + (1.f - z) * e2[eidx];
            } else if (EPI == EPI_ADD) {
                v += e1[(size_t)gr * elds + gc];
            }
            C[(size_t)gr * ldc + gc] = v;
        }
    }
}

// ---------------------------------------------------------------------------
// 3) bidirectional selective scan. thread = (b,d); S=16 states in registers.
//    grid (D/128, B, 2 dirs), block 128.
//    Exploits A[d,s] == (s+1)*A[d,0] (true for these inputs) -> 1 exp/step,
//    with generic 16-exp fallback otherwise.
// ---------------------------------------------------------------------------
__global__ void __launch_bounds__(128)
scan_kernel(const float* __restrict__ Alogf, const float* __restrict__ Alogb,
            const float* __restrict__ Dskf,  const float* __restrict__ Dskb)
{
    const int d   = blockIdx.x * 128 + threadIdx.x;
    const int b   = blockIdx.y;
    const int dir = blockIdx.z;
    const float* XZ = dir ? g_xzb : g_xzf;
    const float* DT = dir ? g_dtb : g_dtf;
    const float* AL = dir ? Alogb : Alogf;
    const float Dsk = (dir ? Dskb : Dskf)[d];
    float* Y = g_ycat + (size_t)dir * D_;

    float a[S_];
    #pragma unroll
    for (int s = 0; s < S_; s++) a[s] = -expf(AL[d * S_ + s]);
    const float a0 = a[0];
    bool structured = true;
    #pragma unroll
    for (int s = 0; s < S_; s++) {
        float ideal = (float)(s + 1) * a0;
        if (fabsf(a[s] - ideal) > 1e-4f * fabsf(a[s])) structured = false;
    }

    float h[S_];
    #pragma unroll
    for (int s = 0; s < S_; s++) h[s] = 0.f;

    for (int t = 0; t < T_; t++) {
        const int tt = dir ? (T_ - 1 - t) : t;
        const size_t rb = (size_t)b * T_ + tt;
        const float dtv = DT[rb * D_ + d];
        const float u   = g_enc[rb * D_ + d];
        const float du  = dtv * u;

        const float4* v4 = reinterpret_cast<const float4*>(XZ + rb * XZW + DTR_);
        float4 B0 = v4[0], B1 = v4[1], B2 = v4[2], B3 = v4[3];
        float4 C0 = v4[4], C1 = v4[5], C2 = v4[6], C3 = v4[7];
        float bc[16] = {B0.x,B0.y,B0.z,B0.w, B1.x,B1.y,B1.z,B1.w,
                        B2.x,B2.y,B2.z,B2.w, B3.x,B3.y,B3.z,B3.w};
        float cc[16] = {C0.x,C0.y,C0.z,C0.w, C1.x,C1.y,C1.z,C1.w,
                        C2.x,C2.y,C2.z,C2.w, C3.x,C3.y,C3.z,C3.w};

        float P[16];
        if (structured) {
            float q  = __expf(a0 * dtv);
            float q2 = q * q, q4 = q2 * q2, q8 = q4 * q4;
            P[0] = q;        P[1] = q2;       P[2] = q2 * q;   P[3] = q4;
            P[4] = q4 * q;   P[5] = q4 * q2;  P[6] = q4 * P[2];P[7] = q8;
            P[8] = q8 * q;   P[9] = q8 * q2;  P[10]= q8 * P[2];P[11]= q8 * q4;
            P[12]= q8 * P[4];P[13]= q8 * P[5];P[14]= q8 * P[6];P[15]= q8 * q8;
        } else {
            #pragma unroll
            for (int s = 0; s < 16; s++) P[s] = __expf(a[s] * dtv);
        }

        float acc0 = 0.f, acc1 = 0.f, acc2 = 0.f, acc3 = 0.f;
        #pragma unroll
        for (int s = 0; s < 16; s += 4) {
            h[s+0] = fmaf(P[s+0], h[s+0], du * bc[s+0]);
            h[s+1] = fmaf(P[s+1], h[s+1], du * bc[s+1]);
            h[s+2] = fmaf(P[s+2], h[s+2], du * bc[s+2]);
            h[s+3] = fmaf(P[s+3], h[s+3], du * bc[s+3]);
            acc0 = fmaf(h[s+0], cc[s+0], acc0);
            acc1 = fmaf(h[s+1], cc[s+1], acc1);
            acc2 = fmaf(h[s+2], cc[s+2], acc2);
            acc3 = fmaf(h[s+3], cc[s+3], acc3);
        }
        Y[rb * (2 * D_) + d] = (acc0 + acc1) + (acc2 + acc3) + u * Dsk;
    }
}

// ---------------------------------------------------------------------------
// 4) LayerNorm over D (one block per row)
// ---------------------------------------------------------------------------
__global__ void ln_kernel(const float* __restrict__ gamma, const float* __restrict__ beta)
{
    __shared__ float r1[256];
    __shared__ float r2[256];
    __shared__ float mu_s, rs_s;
    const int row = blockIdx.x;
    const int tid = threadIdx.x;
    const float* hr = g_hbuf + (size_t)row * D_;
    float v0 = hr[tid], v1 = hr[tid + 256];
    r1[tid] = v0 + v1;
    r2[tid] = v0 * v0 + v1 * v1;
    __syncthreads();
    for (int off = 128; off > 0; off >>= 1) {
        if (tid < off) { r1[tid] += r1[tid + off]; r2[tid] += r2[tid + off]; }
        __syncthreads();
    }
    if (tid == 0) {
        float mu  = r1[0] / (float)D_;
        float var = r2[0] / (float)D_ - mu * mu;
        mu_s = mu;
        rs_s = rsqrtf(var + 1e-5f);
    }
    __syncthreads();
    float mu = mu_s, rs = rs_s;
    g_hn[(size_t)row * D_ + tid]       = (v0 - mu) * rs * gamma[tid]       + beta[tid];
    g_hn[(size_t)row * D_ + tid + 256] = (v1 - mu) * rs * gamma[tid + 256] + beta[tid + 256];
}

// ---------------------------------------------------------------------------
// 5) transpose + de-normalize into output (B, PRED, N)
// ---------------------------------------------------------------------------
__global__ void out_kernel(float* __restrict__ out)
{
    int idx = blockIdx.x * 256 + threadIdx.x;
    if (idx >= B_ * PRED_ * N_) return;
    int n = idx % N_;
    int p = (idx / N_) % PRED_;
    int b = idx / (N_ * PRED_);
    float v = g_pre[((size_t)b * T_ + n) * PRED_ + p];
    out[idx] = v * g_std[b * N_ + n] + g_mean[b * N_ + n];
}

// ---------------------------------------------------------------------------
// launch
// ---------------------------------------------------------------------------
extern "C" void kernel_launch(void* const* d_in, const int* in_sizes, int n_in,
                              void* d_out, int out_size)
{
    const float* x_enc  = (const float*)d_in[0];
    const float* x_mark = (const float*)d_in[1];
    const float* W_emb  = (const float*)d_in[4];
    const float* b_emb  = (const float*)d_in[5];
    const float* Alogf  = (const float*)d_in[6];
    const float* Wx_f   = (const float*)d_in[7];
    const float* Wdt_f  = (const float*)d_in[8];
    const float* bdt_f  = (const float*)d_in[9];
    const float* Dsk_f  = (const float*)d_in[10];
    const float* Alogb  = (const float*)d_in[11];
    const float* Wx_b   = (const float*)d_in[12];
    const float* Wdt_b  = (const float*)d_in[13];
    const float* bdt_b  = (const float*)d_in[14];
    const float* Dsk_b  = (const float*)d_in[15];
    const float* Wz     = (const float*)d_in[16];
    const float* bz     = (const float*)d_in[17];
    const float* Wo     = (const float*)d_in[18];
    const float* bo     = (const float*)d_in[19];
    const float* lng    = (const float*)d_in[20];
    const float* lnb    = (const float*)d_in[21];
    const float* Wproj  = (const float*)d_in[22];
    const float* bproj  = (const float*)d_in[23];
    float* out = (float*)d_out;

    float *tok, *enc, *xzf, *xzb, *dtf, *dtb, *ycat, *fused, *hb, *hn, *pre;
    cudaGetSymbolAddress((void**)&tok,   g_tok);
    cudaGetSymbolAddress((void**)&enc,   g_enc);
    cudaGetSymbolAddress((void**)&xzf,   g_xzf);
    cudaGetSymbolAddress((void**)&xzb,   g_xzb);
    cudaGetSymbolAddress((void**)&dtf,   g_dtf);
    cudaGetSymbolAddress((void**)&dtb,   g_dtb);
    cudaGetSymbolAddress((void**)&ycat,  g_ycat);
    cudaGetSymbolAddress((void**)&fused, g_fused);
    cudaGetSymbolAddress((void**)&hb,    g_hbuf);
    cudaGetSymbolAddress((void**)&hn,    g_hn);
    cudaGetSymbolAddress((void**)&pre,   g_pre);

    const int gy = (MROWS + 127) / 128;   // 41

    // 1) stats
    stats_kernel<<<dim3(B_, (N_ + 31) / 32), 256>>>(x_enc);

    // 2) tok
    build_tok<<<dim3((T_ + 31) / 32, L_ / 32, B_), dim3(32, 8)>>>(x_enc, x_mark);

    // 3) enc = tok @ W_emb + b_emb
    gemm_k<128,128,8,8,8,EPI_NONE><<<dim3(D_ / 128, gy), 256>>>(
        tok, L_, W_emb, D_, enc, D_, MROWS, D_, L_, b_emb, nullptr, nullptr, 0);

    // 4) xz = enc @ Wx  (both directions)
    gemm_k<128,64,8,8,4,EPI_NONE><<<dim3(1, gy), 256>>>(
        enc, D_, Wx_f, XZW, xzf, XZW, MROWS, XZW, D_, nullptr, nullptr, nullptr, 0);
    gemm_k<128,64,8,8,4,EPI_NONE><<<dim3(1, gy), 256>>>(
        enc, D_, Wx_b, XZW, xzb, XZW, MROWS, XZW, D_, nullptr, nullptr, nullptr, 0);

    // 5) dt = softplus(xz[:, :32] @ Wdt + bdt)
    gemm_k<128,128,8,8,8,EPI_SOFTPLUS><<<dim3(D_ / 128, gy), 256>>>(
        xzf, XZW, Wdt_f, D_, dtf, D_, MROWS, D_, DTR_, bdt_f, nullptr, nullptr, 0);
    gemm_k<128,128,8,8,8,EPI_SOFTPLUS><<<dim3(D_ / 128, gy), 256>>>(
        xzb, XZW, Wdt_b, D_, dtb, D_, MROWS, D_, DTR_, bdt_b, nullptr, nullptr, 0);

    // 6) bidirectional scan -> g_ycat = [yf | yb]
    scan_kernel<<<dim3(D_ / 128, B_, 2), 128>>>(Alogf, Alogb, Dsk_f, Dsk_b);

    // 7) fused = sigmoid(ycat @ Wz + bz) gating of yf/yb
    gemm_k<128,128,8,8,8,EPI_SIGFUSE><<<dim3(D_ / 128, gy), 256>>>(
        ycat, 2 * D_, Wz, D_, fused, D_, MROWS, D_, 2 * D_, bz, ycat, ycat + D_, 2 * D_);

    // 8) h = enc + fused @ Wo + bo
    gemm_k<128,128,8,8,8,EPI_ADD><<<dim3(D_ / 128, gy), 256>>>(
        fused, D_, Wo, D_, hb, D_, MROWS, D_, D_, bo, enc, nullptr, D_);

    // 9) layernorm
    ln_kernel<<<MROWS, 256>>>(lng, lnb);

    // 10) pre = hn @ W_proj + b_proj
    gemm_k<128,64,8,8,4,EPI_NONE><<<dim3((PRED_ + 63) / 64, gy), 256>>>(
        hn, D_, Wproj, PRED_, pre, PRED_, MROWS, PRED_, D_, bproj, nullptr, nullptr, 0);

    // 11) output transpose + de-normalize
    out_kernel<<<(B_ * PRED_ * N_ + 255) / 256, 256>>>(out);
}

// round 2
// speedup vs baseline: 1.2589x; 1.2589x over previous
#include <cuda_runtime.h>
#include <math.h>
#include <stdint.h>

// ---------------------------------------------------------------------------
// Problem dims
// ---------------------------------------------------------------------------
namespace {
constexpr int B_   = 16;
constexpr int L_   = 512;
constexpr int N_   = 321;
constexpr int MK_  = 4;
constexpr int D_   = 512;
constexpr int S_   = 16;
constexpr int DTR_ = 32;
constexpr int PRED_= 96;
constexpr int T_   = N_ + MK_;        // 325
constexpr int MROWS = B_ * T_;        // 5200
constexpr int XZW  = DTR_ + 2 * S_;   // 64
}

// ---------------------------------------------------------------------------
// Scratch
// ---------------------------------------------------------------------------
__device__ float g_mean[B_ * N_];
__device__ float g_istd[B_ * N_];
__device__ float g_std [B_ * N_];
__device__ float g_tok  [(size_t)MROWS * L_];
__device__ float g_enc  [(size_t)MROWS * D_];
__device__ float g_xzf  [(size_t)MROWS * XZW];
__device__ float g_xzb  [(size_t)MROWS * XZW];
__device__ float g_dtf  [(size_t)MROWS * D_];
__device__ float g_dtb  [(size_t)MROWS * D_];
__device__ float g_ycat [(size_t)MROWS * 2 * D_];   // [yf | yb]
__device__ float g_fused[(size_t)MROWS * D_];
__device__ float g_hbuf [(size_t)MROWS * D_];
__device__ float g_hn   [(size_t)MROWS * D_];
__device__ float g_pre  [(size_t)MROWS * PRED_];

// ---------------------------------------------------------------------------
// 1) per-(b,n) mean / std over L
// ---------------------------------------------------------------------------
__global__ void stats_kernel(const float* __restrict__ x)
{
    __shared__ float sh1[8][32];
    __shared__ float sh2[8][32];
    const int b  = blockIdx.x;
    const int tx = threadIdx.x & 31;
    const int lg = threadIdx.x >> 5;
    const int n  = blockIdx.y * 32 + tx;

    float s = 0.f, s2 = 0.f;
    if (n < N_) {
        #pragma unroll 4
        for (int l = lg; l < L_; l += 8) {
            float v = x[((size_t)b * L_ + l) * N_ + n];
            s  += v;
            s2 += v * v;
        }
    }
    sh1[lg][tx] = s;
    sh2[lg][tx] = s2;
    __syncthreads();
    if (lg == 0 && n < N_) {
        float S1 = 0.f, S2 = 0.f;
        #pragma unroll
        for (int r = 0; r < 8; r++) { S1 += sh1[r][tx]; S2 += sh2[r][tx]; }
        float mu  = S1 / (float)L_;
        float var = S2 / (float)L_ - mu * mu;
        float sd  = sqrtf(var + 1e-5f);
        g_mean[b * N_ + n] = mu;
        g_std [b * N_ + n] = sd;
        g_istd[b * N_ + n] = 1.f / sd;
    }
}

// ---------------------------------------------------------------------------
// 2) tok build (tiled transpose + normalize)
// ---------------------------------------------------------------------------
__global__ void build_tok(const float* __restrict__ xe, const float* __restrict__ xm)
{
    __shared__ float tile[32][33];
    const int b  = blockIdx.z;
    const int tx = threadIdx.x, ty = threadIdx.y;
    const int t0 = blockIdx.x * 32;
    const int l0 = blockIdx.y * 32;

    #pragma unroll
    for (int j = 0; j < 4; j++) {
        int l = l0 + ty + 8 * j;
        int t = t0 + tx;
        float v = 0.f;
        if (t < T_) {
            if (t < N_) v = (xe[((size_t)b * L_ + l) * N_ + t] - g_mean[b * N_ + t]) * g_istd[b * N_ + t];
            else        v = xm[((size_t)b * L_ + l) * MK_ + (t - N_)];
        }
        tile[ty + 8 * j][tx] = v;
    }
    __syncthreads();
    #pragma unroll
    for (int j = 0; j < 4; j++) {
        int t = t0 + ty + 8 * j;
        int l = l0 + tx;
        if (t < T_) g_tok[((size_t)b * T_ + t) * L_ + l] = tile[tx][ty + 8 * j];
    }
}

// ---------------------------------------------------------------------------
// tf32 helpers (3xTF32 split for ~fp32 accuracy on tensor cores)
// ---------------------------------------------------------------------------
__device__ __forceinline__ void split_tf32(float v, uint32_t& hi, uint32_t& lo)
{
    uint32_t h;
    asm("cvt.rna.tf32.f32 %0, %1;" : "=r"(h) : "f"(v));
    float r = v - __uint_as_float(h);
    uint32_t lw;
    asm("cvt.rna.tf32.f32 %0, %1;" : "=r"(lw) : "f"(r));
    hi = h; lo = lw;
}

__device__ __forceinline__ void mma_tf32(float* c, const uint32_t* a, uint32_t b0, uint32_t b1)
{
    asm volatile(
        "mma.sync.aligned.m16n8k8.row.col.f32.tf32.tf32.f32 "
        "{%0,%1,%2,%3},{%4,%5,%6,%7},{%8,%9},{%0,%1,%2,%3};\n"
        : "+f"(c[0]), "+f"(c[1]), "+f"(c[2]), "+f"(c[3])
        : "r"(a[0]), "r"(a[1]), "r"(a[2]), "r"(a[3]), "r"(b0), "r"(b1));
}

// ---------------------------------------------------------------------------
// Tensor-core GEMM (tf32 3x split). C[M,N] = A[M,K] @ B[K,N] (+bias)(+epi)
// BM=128 BN=128 BK=32, 512 threads (16 warps, 4x4 warp grid, 32x32 warp tile)
// ---------------------------------------------------------------------------
constexpr int EPI_NONE = 0, EPI_SOFTPLUS = 1, EPI_SIGFUSE = 2, EPI_ADD = 3;

template<int EPI>
__global__ void __launch_bounds__(512)
gemm_tc(const float* __restrict__ A, int lda,
        const float* __restrict__ Bm, int ldb,
        float* __restrict__ C, int ldc,
        int M, int Ncols, int K,
        const float* __restrict__ bias,
        const float* __restrict__ e1,
        const float* __restrict__ e2,
        int elds)
{
    constexpr int BM = 128, BN = 128, BK = 32;
    constexpr int LDA_S = 36;   // conflict-free pad (4*g + tg unique mod 32)
    constexpr int LDB_S = 136;  // conflict-free pad (8*tg + g unique mod 32)
    __shared__ float As[BM * LDA_S];
    __shared__ float Bs[BK * LDB_S];

    const int tid = threadIdx.x;
    const int w   = tid >> 5, l = tid & 31;
    const int g   = l >> 2, tg = l & 3;
    const int wr  = w >> 2, wc = w & 3;
    const int m0w = wr * 32, n0w = wc * 32;
    const int rowBase = blockIdx.y * BM;
    const int colBase = blockIdx.x * BN;

    float acc[2][4][4];
    #pragma unroll
    for (int mi = 0; mi < 2; mi++)
        #pragma unroll
        for (int ni = 0; ni < 4; ni++)
            #pragma unroll
            for (int q = 0; q < 4; q++) acc[mi][ni][q] = 0.f;

    // prefetch registers: A tile 128x32 = 1024 float4, B tile 32x128 = 1024 float4
    float4 pa[2], pb[2];

    {
        #pragma unroll
        for (int j = 0; j < 2; j++) {
            int idx = tid + j * 512;
            int row = idx >> 3, kq = idx & 7;
            int gr = rowBase + row;
            float4 v = make_float4(0.f, 0.f, 0.f, 0.f);
            if (gr < M) v = *reinterpret_cast<const float4*>(A + (size_t)gr * lda + kq * 4);
            pa[j] = v;
            int brow = idx >> 5, nq = idx & 31;
            int gc = colBase + nq * 4;
            float4 bv = make_float4(0.f, 0.f, 0.f, 0.f);
            if (gc < Ncols) bv = *reinterpret_cast<const float4*>(Bm + (size_t)brow * ldb + gc);
            pb[j] = bv;
        }
    }

    for (int k0 = 0; k0 < K; k0 += BK) {
        // commit prefetched tile to smem
        #pragma unroll
        for (int j = 0; j < 2; j++) {
            int idx = tid + j * 512;
            int row = idx >> 3, kq = idx & 7;
            *reinterpret_cast<float4*>(As + row * LDA_S + kq * 4) = pa[j];
            int brow = idx >> 5, nq = idx & 31;
            *reinterpret_cast<float4*>(Bs + brow * LDB_S + nq * 4) = pb[j];
        }
        __syncthreads();

        // prefetch next tile
        if (k0 + BK < K) {
            int kn = k0 + BK;
            #pragma unroll
            for (int j = 0; j < 2; j++) {
                int idx = tid + j * 512;
                int row = idx >> 3, kq = idx & 7;
                int gr = rowBase + row;
                float4 v = make_float4(0.f, 0.f, 0.f, 0.f);
                if (gr < M) v = *reinterpret_cast<const float4*>(A + (size_t)gr * lda + kn + kq * 4);
                pa[j] = v;
                int brow = idx >> 5, nq = idx & 31;
                int gc = colBase + nq * 4;
                float4 bv = make_float4(0.f, 0.f, 0.f, 0.f);
                if (gc < Ncols) bv = *reinterpret_cast<const float4*>(Bm + (size_t)(kn + brow) * ldb + gc);
                pb[j] = bv;
            }
        }

        // compute 4 k-chunks of 8
        #pragma unroll
        for (int kc = 0; kc < 4; kc++) {
            const int kk = kc * 8;
            uint32_t ah[2][4], al[2][4];
            #pragma unroll
            for (int mi = 0; mi < 2; mi++) {
                const int r0 = m0w + mi * 16;
                float v0 = As[(r0 + g    ) * LDA_S + kk + tg    ];
                float v1 = As[(r0 + g + 8) * LDA_S + kk + tg    ];
                float v2 = As[(r0 + g    ) * LDA_S + kk + tg + 4];
                float v3 = As[(r0 + g + 8) * LDA_S + kk + tg + 4];
                split_tf32(v0, ah[mi][0], al[mi][0]);
                split_tf32(v1, ah[mi][1], al[mi][1]);
                split_tf32(v2, ah[mi][2], al[mi][2]);
                split_tf32(v3, ah[mi][3], al[mi][3]);
            }
            #pragma unroll
            for (int ni = 0; ni < 4; ni++) {
                const int ccol = n0w + ni * 8 + g;
                float bv0 = Bs[(kk + tg    ) * LDB_S + ccol];
                float bv1 = Bs[(kk + tg + 4) * LDB_S + ccol];
                uint32_t bh0, bl0, bh1, bl1;
                split_tf32(bv0, bh0, bl0);
                split_tf32(bv1, bh1, bl1);
                #pragma unroll
                for (int mi = 0; mi < 2; mi++) {
                    mma_tf32(acc[mi][ni], ah[mi], bl0, bl1);   // Ah*Bl
                    mma_tf32(acc[mi][ni], al[mi], bh0, bh1);   // Al*Bh
                    mma_tf32(acc[mi][ni], ah[mi], bh0, bh1);   // Ah*Bh
                }
            }
        }
        __syncthreads();
    }

    // epilogue
    #pragma unroll
    for (int mi = 0; mi < 2; mi++) {
        #pragma unroll
        for (int half = 0; half < 2; half++) {
            int gr = rowBase + m0w + mi * 16 + g + half * 8;
            if (gr >= M) continue;
            #pragma unroll
            for (int ni = 0; ni < 4; ni++) {
                int gc = colBase + n0w + ni * 8 + 2 * tg;
                if (gc >= Ncols) continue;
                float x0 = acc[mi][ni][half * 2 + 0];
                float x1 = acc[mi][ni][half * 2 + 1];
                if (bias) { x0 += bias[gc]; x1 += bias[gc + 1]; }
                if (EPI == EPI_SOFTPLUS) {
                    x0 = (x0 > 15.f) ? x0 : log1pf(__expf(x0));
                    x1 = (x1 > 15.f) ? x1 : log1pf(__expf(x1));
                } else if (EPI == EPI_SIGFUSE) {
                    size_t ei = (size_t)gr * elds + gc;
                    float z0 = 1.f / (1.f + __expf(-x0));
                    float z1 = 1.f / (1.f + __expf(-x1));
                    x0 = z0 * e1[ei]     + (1.f - z0) * e2[ei];
                    x1 = z1 * e1[ei + 1] + (1.f - z1) * e2[ei + 1];
                } else if (EPI == EPI_ADD) {
                    size_t ei = (size_t)gr * elds + gc;
                    x0 += e1[ei];
                    x1 += e1[ei + 1];
                }
                C[(size_t)gr * ldc + gc]     = x0;
                C[(size_t)gr * ldc + gc + 1] = x1;
            }
        }
    }
}

// ---------------------------------------------------------------------------
// SIMT GEMM (for skinny shapes), dual-direction via blockIdx.z
// ---------------------------------------------------------------------------
template<int BM, int BN, int BK, int TM, int TN, int EPI>
__global__ void __launch_bounds__((BM / TM) * (BN / TN))
gemm_k(const float* __restrict__ A,  const float* __restrict__ A2, int lda,
       const float* __restrict__ Bm, const float* __restrict__ Bm2, int ldb,
       float* __restrict__ C, float* __restrict__ C2, int ldc,
       int M, int Ncols, int K,
       const float* __restrict__ bias, const float* __restrict__ bias2)
{
    if (blockIdx.z == 1) { A = A2; Bm = Bm2; C = C2; bias = bias2; }
    constexpr int THREADS = (BM / TM) * (BN / TN);
    __shared__ float As[BK][BM];
    __shared__ float Bs[BK][BN];
    const int tid  = threadIdx.x;
    const int tcol = tid % (BN / TN);
    const int trow = tid / (BN / TN);
    const int rowBase = blockIdx.y * BM;
    const int colBase = blockIdx.x * BN;

    float acc[TM][TN];
    #pragma unroll
    for (int i = 0; i < TM; i++)
        #pragma unroll
        for (int j = 0; j < TN; j++) acc[i][j] = 0.f;

    for (int k0 = 0; k0 < K; k0 += BK) {
        for (int i = tid; i < BM * (BK / 4); i += THREADS) {
            int row = i / (BK / 4);
            int kq  = i % (BK / 4);
            float4 v = make_float4(0.f, 0.f, 0.f, 0.f);
            int gr = rowBase + row;
            if (gr < M) v = *reinterpret_cast<const float4*>(A + (size_t)gr * lda + k0 + kq * 4);
            As[kq * 4 + 0][row] = v.x;
            As[kq * 4 + 1][row] = v.y;
            As[kq * 4 + 2][row] = v.z;
            As[kq * 4 + 3][row] = v.w;
        }
        for (int i = tid; i < BK * (BN / 4); i += THREADS) {
            int kr = i / (BN / 4);
            int nq = i % (BN / 4);
            int gc = colBase + nq * 4;
            float4 v = make_float4(0.f, 0.f, 0.f, 0.f);
            if (gc < Ncols) v = *reinterpret_cast<const float4*>(Bm + (size_t)(k0 + kr) * ldb + gc);
            *reinterpret_cast<float4*>(&Bs[kr][nq * 4]) = v;
        }
        __syncthreads();
        #pragma unroll
        for (int k = 0; k < BK; k++) {
            float rm[TM], rn[TN];
            #pragma unroll
            for (int i = 0; i < TM; i++) rm[i] = As[k][trow * TM + i];
            #pragma unroll
            for (int j = 0; j < TN; j++) rn[j] = Bs[k][tcol * TN + j];
            #pragma unroll
            for (int i = 0; i < TM; i++)
                #pragma unroll
                for (int j = 0; j < TN; j++) acc[i][j] = fmaf(rm[i], rn[j], acc[i][j]);
        }
        __syncthreads();
    }

    #pragma unroll
    for (int i = 0; i < TM; i++) {
        int gr = rowBase + trow * TM + i;
        if (gr >= M) continue;
        #pragma unroll
        for (int j = 0; j < TN; j++) {
            int gc = colBase + tcol * TN + j;
            if (gc >= Ncols) continue;
            float v = acc[i][j];
            if (bias) v += bias[gc];
            if (EPI == EPI_SOFTPLUS) v = (v > 15.f) ? v : log1pf(__expf(v));
            C[(size_t)gr * ldc + gc] = v;
        }
    }
}

// ---------------------------------------------------------------------------
// 3) bidirectional selective scan
// ---------------------------------------------------------------------------
__global__ void __launch_bounds__(128)
scan_kernel(const float* __restrict__ Alogf, const float* __restrict__ Alogb,
            const float* __restrict__ Dskf,  const float* __restrict__ Dskb)
{
    const int d   = blockIdx.x * 128 + threadIdx.x;
    const int b   = blockIdx.y;
    const int dir = blockIdx.z;
    const float* XZ = dir ? g_xzb : g_xzf;
    const float* DT = dir ? g_dtb : g_dtf;
    const float* AL = dir ? Alogb : Alogf;
    const float Dsk = (dir ? Dskb : Dskf)[d];
    float* Y = g_ycat + (size_t)dir * D_;

    float a[S_];
    #pragma unroll
    for (int s = 0; s < S_; s++) a[s] = -expf(AL[d * S_ + s]);
    const float a0 = a[0];
    bool structured = true;
    #pragma unroll
    for (int s = 0; s < S_; s++) {
        float ideal = (float)(s + 1) * a0;
        if (fabsf(a[s] - ideal) > 1e-4f * fabsf(a[s])) structured = false;
    }

    float h[S_];
    #pragma unroll
    for (int s = 0; s < S_; s++) h[s] = 0.f;

    for (int t = 0; t < T_; t++) {
        const int tt = dir ? (T_ - 1 - t) : t;
        const size_t rb = (size_t)b * T_ + tt;
        const float dtv = DT[rb * D_ + d];
        const float u   = g_enc[rb * D_ + d];
        const float du  = dtv * u;

        const float4* v4 = reinterpret_cast<const float4*>(XZ + rb * XZW + DTR_);
        float4 B0 = v4[0], B1 = v4[1], B2 = v4[2], B3 = v4[3];
        float4 C0 = v4[4], C1 = v4[5], C2 = v4[6], C3 = v4[7];
        float bc[16] = {B0.x,B0.y,B0.z,B0.w, B1.x,B1.y,B1.z,B1.w,
                        B2.x,B2.y,B2.z,B2.w, B3.x,B3.y,B3.z,B3.w};
        float cc[16] = {C0.x,C0.y,C0.z,C0.w, C1.x,C1.y,C1.z,C1.w,
                        C2.x,C2.y,C2.z,C2.w, C3.x,C3.y,C3.z,C3.w};

        float P[16];
        if (structured) {
            float q  = __expf(a0 * dtv);
            float q2 = q * q, q4 = q2 * q2, q8 = q4 * q4;
            P[0] = q;        P[1] = q2;       P[2] = q2 * q;   P[3] = q4;
            P[4] = q4 * q;   P[5] = q4 * q2;  P[6] = q4 * P[2];P[7] = q8;
            P[8] = q8 * q;   P[9] = q8 * q2;  P[10]= q8 * P[2];P[11]= q8 * q4;
            P[12]= q8 * P[4];P[13]= q8 * P[5];P[14]= q8 * P[6];P[15]= q8 * q8;
        } else {
            #pragma unroll
            for (int s = 0; s < 16; s++) P[s] = __expf(a[s] * dtv);
        }

        float acc0 = 0.f, acc1 = 0.f, acc2 = 0.f, acc3 = 0.f;
        #pragma unroll
        for (int s = 0; s < 16; s += 4) {
            h[s+0] = fmaf(P[s+0], h[s+0], du * bc[s+0]);
            h[s+1] = fmaf(P[s+1], h[s+1], du * bc[s+1]);
            h[s+2] = fmaf(P[s+2], h[s+2], du * bc[s+2]);
            h[s+3] = fmaf(P[s+3], h[s+3], du * bc[s+3]);
            acc0 = fmaf(h[s+0], cc[s+0], acc0);
            acc1 = fmaf(h[s+1], cc[s+1], acc1);
            acc2 = fmaf(h[s+2], cc[s+2], acc2);
            acc3 = fmaf(h[s+3], cc[s+3], acc3);
        }
        Y[rb * (2 * D_) + d] = (acc0 + acc1) + (acc2 + acc3) + u * Dsk;
    }
}

// ---------------------------------------------------------------------------
// 4) LayerNorm over D
// ---------------------------------------------------------------------------
__global__ void ln_kernel(const float* __restrict__ gamma, const float* __restrict__ beta)
{
    __shared__ float r1[256];
    __shared__ float r2[256];
    __shared__ float mu_s, rs_s;
    const int row = blockIdx.x;
    const int tid = threadIdx.x;
    const float* hr = g_hbuf + (size_t)row * D_;
    float v0 = hr[tid], v1 = hr[tid + 256];
    r1[tid] = v0 + v1;
    r2[tid] = v0 * v0 + v1 * v1;
    __syncthreads();
    for (int off = 128; off > 0; off >>= 1) {
        if (tid < off) { r1[tid] += r1[tid + off]; r2[tid] += r2[tid + off]; }
        __syncthreads();
    }
    if (tid == 0) {
        float mu  = r1[0] / (float)D_;
        float var = r2[0] / (float)D_ - mu * mu;
        mu_s = mu;
        rs_s = rsqrtf(var + 1e-5f);
    }
    __syncthreads();
    float mu = mu_s, rs = rs_s;
    g_hn[(size_t)row * D_ + tid]       = (v0 - mu) * rs * gamma[tid]       + beta[tid];
    g_hn[(size_t)row * D_ + tid + 256] = (v1 - mu) * rs * gamma[tid + 256] + beta[tid + 256];
}

// ---------------------------------------------------------------------------
// 5) transpose + de-normalize into output (B, PRED, N)
// ---------------------------------------------------------------------------
__global__ void out_kernel(float* __restrict__ out)
{
    int idx = blockIdx.x * 256 + threadIdx.x;
    if (idx >= B_ * PRED_ * N_) return;
    int n = idx % N_;
    int p = (idx / N_) % PRED_;
    int b = idx / (N_ * PRED_);
    float v = g_pre[((size_t)b * T_ + n) * PRED_ + p];
    out[idx] = v * g_std[b * N_ + n] + g_mean[b * N_ + n];
}

// ---------------------------------------------------------------------------
// launch
// ---------------------------------------------------------------------------
extern "C" void kernel_launch(void* const* d_in, const int* in_sizes, int n_in,
                              void* d_out, int out_size)
{
    const float* x_enc  = (const float*)d_in[0];
    const float* x_mark = (const float*)d_in[1];
    const float* W_emb  = (const float*)d_in[4];
    const float* b_emb  = (const float*)d_in[5];
    const float* Alogf  = (const float*)d_in[6];
    const float* Wx_f   = (const float*)d_in[7];
    const float* Wdt_f  = (const float*)d_in[8];
    const float* bdt_f  = (const float*)d_in[9];
    const float* Dsk_f  = (const float*)d_in[10];
    const float* Alogb  = (const float*)d_in[11];
    const float* Wx_b   = (const float*)d_in[12];
    const float* Wdt_b  = (const float*)d_in[13];
    const float* bdt_b  = (const float*)d_in[14];
    const float* Dsk_b  = (const float*)d_in[15];
    const float* Wz     = (const float*)d_in[16];
    const float* bz     = (const float*)d_in[17];
    const float* Wo     = (const float*)d_in[18];
    const float* bo     = (const float*)d_in[19];
    const float* lng    = (const float*)d_in[20];
    const float* lnb    = (const float*)d_in[21];
    const float* Wproj  = (const float*)d_in[22];
    const float* bproj  = (const float*)d_in[23];
    float* out = (float*)d_out;

    float *tok, *enc, *xzf, *xzb, *dtf, *dtb, *ycat, *fused, *hb, *hn, *pre;
    cudaGetSymbolAddress((void**)&tok,   g_tok);
    cudaGetSymbolAddress((void**)&enc,   g_enc);
    cudaGetSymbolAddress((void**)&xzf,   g_xzf);
    cudaGetSymbolAddress((void**)&xzb,   g_xzb);
    cudaGetSymbolAddress((void**)&dtf,   g_dtf);
    cudaGetSymbolAddress((void**)&dtb,   g_dtb);
    cudaGetSymbolAddress((void**)&ycat,  g_ycat);
    cudaGetSymbolAddress((void**)&fused, g_fused);
    cudaGetSymbolAddress((void**)&hb,    g_hbuf);
    cudaGetSymbolAddress((void**)&hn,    g_hn);
    cudaGetSymbolAddress((void**)&pre,   g_pre);

    const int gy128 = (MROWS + 127) / 128;   // 41
    const int gy64  = (MROWS + 63) / 64;     // 82

    // 1) stats
    stats_kernel<<<dim3(B_, (N_ + 31) / 32), 256>>>(x_enc);

    // 2) tok
    build_tok<<<dim3((T_ + 31) / 32, L_ / 32, B_), dim3(32, 8)>>>(x_enc, x_mark);

    // 3) enc = tok @ W_emb + b_emb   [TC]
    gemm_tc<EPI_NONE><<<dim3(D_ / 128, gy128), 512>>>(
        tok, L_, W_emb, D_, enc, D_, MROWS, D_, L_, b_emb, nullptr, nullptr, 0);

    // 4) xz = enc @ Wx (both directions in one launch)
    gemm_k<64,64,8,4,4,EPI_NONE><<<dim3(1, gy64, 2), 256>>>(
        enc, enc, D_, Wx_f, Wx_b, XZW, xzf, xzb, XZW, MROWS, XZW, D_,
        nullptr, nullptr);

    // 5) dt = softplus(xz[:, :32] @ Wdt + bdt) (both directions)
    gemm_k<128,128,8,8,8,EPI_SOFTPLUS><<<dim3(D_ / 128, gy128, 2), 256>>>(
        xzf, xzb, XZW, Wdt_f, Wdt_b, D_, dtf, dtb, D_, MROWS, D_, DTR_,
        bdt_f, bdt_b);

    // 6) bidirectional scan -> g_ycat = [yf | yb]
    scan_kernel<<<dim3(D_ / 128, B_, 2), 128>>>(Alogf, Alogb, Dsk_f, Dsk_b);

    // 7) fused = sigmoid(ycat @ Wz + bz) gating of yf/yb  [TC]
    gemm_tc<EPI_SIGFUSE><<<dim3(D_ / 128, gy128), 512>>>(
        ycat, 2 * D_, Wz, D_, fused, D_, MROWS, D_, 2 * D_, bz,
        ycat, ycat + D_, 2 * D_);

    // 8) h = enc + fused @ Wo + bo   [TC]
    gemm_tc<EPI_ADD><<<dim3(D_ / 128, gy128), 512>>>(
        fused, D_, Wo, D_, hb, D_, MROWS, D_, D_, bo, enc, nullptr, D_);

    // 9) layernorm
    ln_kernel<<<MROWS, 256>>>(lng, lnb);

    // 10) pre = hn @ W_proj + b_proj
    gemm_k<64,64,8,4,4,EPI_NONE><<<dim3((PRED_ + 63) / 64, gy64, 1), 256>>>(
        hn, nullptr, D_, Wproj, nullptr, PRED_, pre, nullptr, PRED_,
        MROWS, PRED_, D_, bproj, nullptr);

    // 11) output transpose + de-normalize
    out_kernel<<<(B_ * PRED_ * N_ + 255) / 256, 256>>>(out);
}

// round 4
// speedup vs baseline: 1.6683x; 1.3253x over previous
#include <cuda_runtime.h>
#include <math.h>
#include <stdint.h>

// ---------------------------------------------------------------------------
// Problem dims
// ---------------------------------------------------------------------------
namespace {
constexpr int B_   = 16;
constexpr int L_   = 512;
constexpr int N_   = 321;
constexpr int MK_  = 4;
constexpr int D_   = 512;
constexpr int S_   = 16;
constexpr int DTR_ = 32;
constexpr int PRED_= 96;
constexpr int T_   = N_ + MK_;        // 325
constexpr int MROWS = B_ * T_;        // 5200
constexpr int NC_  = 13;              // scan chunks
constexpr int CH_  = 25;              // steps per chunk (13*25 = 325)
}

// ---------------------------------------------------------------------------
// Scratch
// ---------------------------------------------------------------------------
__device__ float g_mean[B_ * N_];
__device__ float g_istd[B_ * N_];
__device__ float g_std [B_ * N_];
__device__ float g_tok  [(size_t)MROWS * L_];
__device__ float g_enc  [(size_t)MROWS * D_];
__device__ float g_xz   [(size_t)MROWS * 128];      // [f(64) | b(64)] per row
__device__ float g_dtcat[(size_t)MROWS * 1024];     // [dt_f(512) | dt_b(512)]
__device__ float g_ycat [(size_t)MROWS * 2 * D_];   // [yf | yb]
__device__ float g_fused[(size_t)MROWS * D_];
__device__ float g_hbuf [(size_t)MROWS * D_];
__device__ float g_hn   [(size_t)MROWS * D_];
__device__ float g_pre  [(size_t)MROWS * PRED_];

// packed weights
__device__ float g_wx [512 * 128];
__device__ float g_wdt[128 * 1024];
__device__ float g_bdt[1024];

// chunked-scan intermediates
__device__ float g_dts [2 * NC_ * B_ * D_];
__device__ float g_hfin[(size_t)2 * NC_ * B_ * S_ * D_];
__device__ float g_h0  [(size_t)2 * NC_ * B_ * S_ * D_];

// ---------------------------------------------------------------------------
// 0) pack weights
// ---------------------------------------------------------------------------
__global__ void pack_kernel(const float* __restrict__ Wxf, const float* __restrict__ Wxb,
                            const float* __restrict__ Wdtf, const float* __restrict__ Wdtb,
                            const float* __restrict__ bdtf, const float* __restrict__ bdtb)
{
    int i = blockIdx.x * 256 + threadIdx.x;
    if (i < 512 * 128) {
        int r = i >> 7, c = i & 127;
        g_wx[i] = (c < 64) ? Wxf[r * 64 + c] : Wxb[r * 64 + (c - 64)];
    }
    if (i < 128 * 1024) {
        int r = i >> 10, c = i & 1023;
        float v = 0.f;
        if (c < 512) { if (r < 32) v = Wdtf[r * 512 + c]; }
        else         { if (r >= 64 && r < 96) v = Wdtb[(r - 64) * 512 + (c - 512)]; }
        g_wdt[i] = v;
    }
    if (i < 1024) g_bdt[i] = (i < 512) ? bdtf[i] : bdtb[i - 512];
}

// ---------------------------------------------------------------------------
// 1) per-(b,n) mean / std over L
// ---------------------------------------------------------------------------
__global__ void stats_kernel(const float* __restrict__ x)
{
    __shared__ float sh1[8][32];
    __shared__ float sh2[8][32];
    const int b  = blockIdx.x;
    const int tx = threadIdx.x & 31;
    const int lg = threadIdx.x >> 5;
    const int n  = blockIdx.y * 32 + tx;

    float s = 0.f, s2 = 0.f;
    if (n < N_) {
        #pragma unroll 4
        for (int l = lg; l < L_; l += 8) {
            float v = x[((size_t)b * L_ + l) * N_ + n];
            s  += v;
            s2 += v * v;
        }
    }
    sh1[lg][tx] = s;
    sh2[lg][tx] = s2;
    __syncthreads();
    if (lg == 0 && n < N_) {
        float S1 = 0.f, S2 = 0.f;
        #pragma unroll
        for (int r = 0; r < 8; r++) { S1 += sh1[r][tx]; S2 += sh2[r][tx]; }
        float mu  = S1 / (float)L_;
        float var = S2 / (float)L_ - mu * mu;
        float sd  = sqrtf(var + 1e-5f);
        g_mean[b * N_ + n] = mu;
        g_std [b * N_ + n] = sd;
        g_istd[b * N_ + n] = 1.f / sd;
    }
}

// ---------------------------------------------------------------------------
// 2) tok build (tiled transpose + normalize)
// ---------------------------------------------------------------------------
__global__ void build_tok(const float* __restrict__ xe, const float* __restrict__ xm)
{
    __shared__ float tile[32][33];
    const int b  = blockIdx.z;
    const int tx = threadIdx.x, ty = threadIdx.y;
    const int t0 = blockIdx.x * 32;
    const int l0 = blockIdx.y * 32;

    #pragma unroll
    for (int j = 0; j < 4; j++) {
        int l = l0 + ty + 8 * j;
        int t = t0 + tx;
        float v = 0.f;
        if (t < T_) {
            if (t < N_) v = (xe[((size_t)b * L_ + l) * N_ + t] - g_mean[b * N_ + t]) * g_istd[b * N_ + t];
            else        v = xm[((size_t)b * L_ + l) * MK_ + (t - N_)];
        }
        tile[ty + 8 * j][tx] = v;
    }
    __syncthreads();
    #pragma unroll
    for (int j = 0; j < 4; j++) {
        int t = t0 + ty + 8 * j;
        int l = l0 + tx;
        if (t < T_) g_tok[((size_t)b * T_ + t) * L_ + l] = tile[tx][ty + 8 * j];
    }
}

// ---------------------------------------------------------------------------
// tf32 helpers (3xTF32 split)
// ---------------------------------------------------------------------------
__device__ __forceinline__ void split_tf32(float v, uint32_t& hi, uint32_t& lo)
{
    uint32_t h;
    asm("cvt.rna.tf32.f32 %0, %1;" : "=r"(h) : "f"(v));
    float r = v - __uint_as_float(h);
    uint32_t lw;
    asm("cvt.rna.tf32.f32 %0, %1;" : "=r"(lw) : "f"(r));
    hi = h; lo = lw;
}

__device__ __forceinline__ void mma_tf32(float* c, const uint32_t* a, uint32_t b0, uint32_t b1)
{
    asm volatile(
        "mma.sync.aligned.m16n8k8.row.col.f32.tf32.tf32.f32 "
        "{%0,%1,%2,%3},{%4,%5,%6,%7},{%8,%9},{%0,%1,%2,%3};\n"
        : "+f"(c[0]), "+f"(c[1]), "+f"(c[2]), "+f"(c[3])
        : "r"(a[0]), "r"(a[1]), "r"(a[2]), "r"(a[3]), "r"(b0), "r"(b1));
}

// ---------------------------------------------------------------------------
// Tensor-core GEMM (tf32, 3x split). BM=64 BN=128 BK=32, 256 threads (8 warps)
// ---------------------------------------------------------------------------
constexpr int EPI_NONE = 0, EPI_SOFTPLUS = 1, EPI_SIGFUSE = 2, EPI_ADD = 3;

template<int EPI>
__global__ void __launch_bounds__(256)
gemm_tc(const float* __restrict__ A, int lda,
        const float* __restrict__ Bm, int ldb,
        float* __restrict__ C, int ldc,
        int M, int Ncols, int K,
        const float* __restrict__ bias,
        const float* __restrict__ e1,
        const float* __restrict__ e2,
        int elds)
{
    constexpr int BM = 64, BN = 128, BK = 32;
    constexpr int LDA_S = 36;
    constexpr int LDB_S = 136;
    __shared__ float As[BM * LDA_S];
    __shared__ float Bs[BK * LDB_S];

    const int tid = threadIdx.x;
    const int w   = tid >> 5, l = tid & 31;
    const int g   = l >> 2, tg = l & 3;
    const int wr  = w >> 2, wc = w & 3;      // 2 x 4 warp grid
    const int m0w = wr * 32, n0w = wc * 32;
    const int rowBase = blockIdx.y * BM;
    const int colBase = blockIdx.x * BN;

    float acc[2][4][4];
    #pragma unroll
    for (int mi = 0; mi < 2; mi++)
        #pragma unroll
        for (int ni = 0; ni < 4; ni++)
            #pragma unroll
            for (int q = 0; q < 4; q++) acc[mi][ni][q] = 0.f;

    float4 pa[2], pb[4];

    // initial prefetch (k0 = 0)
    #pragma unroll
    for (int j = 0; j < 2; j++) {
        int idx = tid + j * 256;
        int row = idx >> 3, kq = idx & 7;
        int gr = rowBase + row;
        float4 v = make_float4(0.f, 0.f, 0.f, 0.f);
        if (gr < M) v = *reinterpret_cast<const float4*>(A + (size_t)gr * lda + kq * 4);
        pa[j] = v;
    }
    #pragma unroll
    for (int j = 0; j < 4; j++) {
        int idx = tid + j * 256;
        int brow = idx >> 5, nq = idx & 31;
        int gc = colBase + nq * 4;
        float4 bv = make_float4(0.f, 0.f, 0.f, 0.f);
        if (gc < Ncols) bv = *reinterpret_cast<const float4*>(Bm + (size_t)brow * ldb + gc);
        pb[j] = bv;
    }

    for (int k0 = 0; k0 < K; k0 += BK) {
        // commit prefetched tile
        #pragma unroll
        for (int j = 0; j < 2; j++) {
            int idx = tid + j * 256;
            int row = idx >> 3, kq = idx & 7;
            *reinterpret_cast<float4*>(As + row * LDA_S + kq * 4) = pa[j];
        }
        #pragma unroll
        for (int j = 0; j < 4; j++) {
            int idx = tid + j * 256;
            int brow = idx >> 5, nq = idx & 31;
            *reinterpret_cast<float4*>(Bs + brow * LDB_S + nq * 4) = pb[j];
        }
        __syncthreads();

        // prefetch next tile
        if (k0 + BK < K) {
            const int kn = k0 + BK;
            #pragma unroll
            for (int j = 0; j < 2; j++) {
                int idx = tid + j * 256;
                int row = idx >> 3, kq = idx & 7;
                int gr = rowBase + row;
                float4 v = make_float4(0.f, 0.f, 0.f, 0.f);
                if (gr < M) v = *reinterpret_cast<const float4*>(A + (size_t)gr * lda + kn + kq * 4);
                pa[j] = v;
            }
            #pragma unroll
            for (int j = 0; j < 4; j++) {
                int idx = tid + j * 256;
                int brow = idx >> 5, nq = idx & 31;
                int gc = colBase + nq * 4;
                float4 bv = make_float4(0.f, 0.f, 0.f, 0.f);
                if (gc < Ncols) bv = *reinterpret_cast<const float4*>(Bm + (size_t)(kn + brow) * ldb + gc);
                pb[j] = bv;
            }
        }

        #pragma unroll
        for (int kc = 0; kc < 4; kc++) {
            const int kk = kc * 8;
            uint32_t ah[2][4], al[2][4];
            #pragma unroll
            for (int mi = 0; mi < 2; mi++) {
                const int r0 = m0w + mi * 16;
                float v0 = As[(r0 + g    ) * LDA_S + kk + tg    ];
                float v1 = As[(r0 + g + 8) * LDA_S + kk + tg    ];
                float v2 = As[(r0 + g    ) * LDA_S + kk + tg + 4];
                float v3 = As[(r0 + g + 8) * LDA_S + kk + tg + 4];
                split_tf32(v0, ah[mi][0], al[mi][0]);
                split_tf32(v1, ah[mi][1], al[mi][1]);
                split_tf32(v2, ah[mi][2], al[mi][2]);
                split_tf32(v3, ah[mi][3], al[mi][3]);
            }
            #pragma unroll
            for (int ni = 0; ni < 4; ni++) {
                const int ccol = n0w + ni * 8 + g;
                float bv0 = Bs[(kk + tg    ) * LDB_S + ccol];
                float bv1 = Bs[(kk + tg + 4) * LDB_S + ccol];
                uint32_t bh0, bl0, bh1, bl1;
                split_tf32(bv0, bh0, bl0);
                split_tf32(bv1, bh1, bl1);
                #pragma unroll
                for (int mi = 0; mi < 2; mi++) {
                    mma_tf32(acc[mi][ni], ah[mi], bl0, bl1);
                    mma_tf32(acc[mi][ni], al[mi], bh0, bh1);
                    mma_tf32(acc[mi][ni], ah[mi], bh0, bh1);
                }
            }
        }
        __syncthreads();
    }

    // epilogue
    #pragma unroll
    for (int mi = 0; mi < 2; mi++) {
        #pragma unroll
        for (int half = 0; half < 2; half++) {
            int gr = rowBase + m0w + mi * 16 + g + half * 8;
            if (gr >= M) continue;
            #pragma unroll
            for (int ni = 0; ni < 4; ni++) {
                int gc = colBase + n0w + ni * 8 + 2 * tg;
                if (gc >= Ncols) continue;
                float x0 = acc[mi][ni][half * 2 + 0];
                float x1 = acc[mi][ni][half * 2 + 1];
                if (bias) { x0 += bias[gc]; x1 += bias[gc + 1]; }
                if (EPI == EPI_SOFTPLUS) {
                    x0 = (x0 > 15.f) ? x0 : log1pf(__expf(x0));
                    x1 = (x1 > 15.f) ? x1 : log1pf(__expf(x1));
                } else if (EPI == EPI_SIGFUSE) {
                    size_t ei = (size_t)gr * elds + gc;
                    float z0 = 1.f / (1.f + __expf(-x0));
                    float z1 = 1.f / (1.f + __expf(-x1));
                    x0 = z0 * e1[ei]     + (1.f - z0) * e2[ei];
                    x1 = z1 * e1[ei + 1] + (1.f - z1) * e2[ei + 1];
                } else if (EPI == EPI_ADD) {
                    size_t ei = (size_t)gr * elds + gc;
                    x0 += e1[ei];
                    x1 += e1[ei + 1];
                }
                C[(size_t)gr * ldc + gc]     = x0;
                C[(size_t)gr * ldc + gc + 1] = x1;
            }
        }
    }
}

// ---------------------------------------------------------------------------
// scan helpers
// ---------------------------------------------------------------------------
__device__ __forceinline__ void load_a(const float* __restrict__ AL, int d,
                                       float* a, float& a0, bool& structured)
{
    #pragma unroll
    for (int s = 0; s < S_; s++) a[s] = -expf(AL[d * S_ + s]);
    a0 = a[0];
    structured = true;
    #pragma unroll
    for (int s = 0; s < S_; s++) {
        float ideal = (float)(s + 1) * a0;
        if (fabsf(a[s] - ideal) > 1e-4f * fabsf(a[s])) structured = false;
    }
}

__device__ __forceinline__ void make_powers(float q, float* P)
{
    float q2 = q * q, q4 = q2 * q2, q8 = q4 * q4;
    P[0] = q;        P[1] = q2;       P[2] = q2 * q;    P[3] = q4;
    P[4] = q4 * q;   P[5] = q4 * q2;  P[6] = q4 * P[2]; P[7] = q8;
    P[8] = q8 * q;   P[9] = q8 * q2;  P[10]= q8 * P[2]; P[11]= q8 * q4;
    P[12]= q8 * P[4];P[13]= q8 * P[5];P[14]= q8 * P[6]; P[15]= q8 * q8;
}

__device__ __forceinline__ void calc_P(bool structured, float a0, const float* a,
                                       float x, float* P)
{
    if (structured) {
        make_powers(__expf(a0 * x), P);
    } else {
        #pragma unroll
        for (int s = 0; s < 16; s++) P[s] = __expf(a[s] * x);
    }
}

// Phase A: per-chunk scan from zero state; store final h and sum(dt)
__global__ void __launch_bounds__(128)
scan_partial(const float* __restrict__ Alogf, const float* __restrict__ Alogb)
{
    const int bx  = blockIdx.x;            // 52 = 4 dblocks * 13 chunks
    const int db  = bx & 3;
    const int c   = bx >> 2;
    const int d   = db * 128 + threadIdx.x;
    const int b   = blockIdx.y;
    const int dir = blockIdx.z;

    float a[S_], a0; bool structured;
    load_a(dir ? Alogb : Alogf, d, a, a0, structured);

    float h[S_];
    #pragma unroll
    for (int s = 0; s < S_; s++) h[s] = 0.f;
    float dts = 0.f;

    for (int t = c * CH_; t < c * CH_ + CH_; t++) {
        const int tt = dir ? (T_ - 1 - t) : t;
        const size_t rb = (size_t)b * T_ + tt;
        const float dtv = g_dtcat[rb * 1024 + dir * 512 + d];
        const float u   = g_enc[rb * D_ + d];
        const float du  = dtv * u;
        dts += dtv;

        const float4* v4 = reinterpret_cast<const float4*>(g_xz + rb * 128 + dir * 64 + 32);
        float4 B0 = v4[0], B1 = v4[1], B2 = v4[2], B3 = v4[3];
        float bc[16] = {B0.x,B0.y,B0.z,B0.w, B1.x,B1.y,B1.z,B1.w,
                        B2.x,B2.y,B2.z,B2.w, B3.x,B3.y,B3.z,B3.w};

        float P[16];
        calc_P(structured, a0, a, dtv, P);

        #pragma unroll
        for (int s = 0; s < 16; s++) h[s] = fmaf(P[s], h[s], du * bc[s]);
    }

    const size_t base = (size_t)(dir * NC_ + c) * B_ + b;
    g_dts[base * D_ + d] = dts;
    #pragma unroll
    for (int s = 0; s < S_; s++)
        g_hfin[(base * S_ + s) * D_ + d] = h[s];
}

// Phase B: sequential combine over chunks; store per-chunk initial states
__global__ void __launch_bounds__(256)
scan_combine(const float* __restrict__ Alogf, const float* __restrict__ Alogb)
{
    const int idx = blockIdx.x * 256 + threadIdx.x;   // 16384 total
    const int dir = idx >> 13;
    const int b   = (idx >> 9) & 15;
    const int d   = idx & 511;

    float a[S_], a0; bool structured;
    load_a(dir ? Alogb : Alogf, d, a, a0, structured);

    float h[S_];
    #pragma unroll
    for (int s = 0; s < S_; s++) h[s] = 0.f;

    for (int c = 0; c < NC_; c++) {
        const size_t base = (size_t)(dir * NC_ + c) * B_ + b;
        #pragma unroll
        for (int s = 0; s < S_; s++)
            g_h0[(base * S_ + s) * D_ + d] = h[s];
        const float dts = g_dts[base * D_ + d];
        float P[16];
        calc_P(structured, a0, a, dts, P);
        #pragma unroll
        for (int s = 0; s < S_; s++)
            h[s] = fmaf(P[s], h[s], g_hfin[(base * S_ + s) * D_ + d]);
    }
}

// Phase C: replay chunk from corrected initial state, write y
__global__ void __launch_bounds__(128)
scan_final(const float* __restrict__ Alogf, const float* __restrict__ Alogb,
           const float* __restrict__ Dskf,  const float* __restrict__ Dskb)
{
    const int bx  = blockIdx.x;
    const int db  = bx & 3;
    const int c   = bx >> 2;
    const int d   = db * 128 + threadIdx.x;
    const int b   = blockIdx.y;
    const int dir = blockIdx.z;

    float a[S_], a0; bool structured;
    load_a(dir ? Alogb : Alogf, d, a, a0, structured);
    const float Dsk = (dir ? Dskb : Dskf)[d];

    const size_t base = (size_t)(dir * NC_ + c) * B_ + b;
    float h[S_];
    #pragma unroll
    for (int s = 0; s < S_; s++)
        h[s] = g_h0[(base * S_ + s) * D_ + d];

    for (int t = c * CH_; t < c * CH_ + CH_; t++) {
        const int tt = dir ? (T_ - 1 - t) : t;
        const size_t rb = (size_t)b * T_ + tt;
        const float dtv = g_dtcat[rb * 1024 + dir * 512 + d];
        const float u   = g_enc[rb * D_ + d];
        const float du  = dtv * u;

        const float4* v4 = reinterpret_cast<const float4*>(g_xz + rb * 128 + dir * 64 + 32);
        float4 B0 = v4[0], B1 = v4[1], B2 = v4[2], B3 = v4[3];
        float4 C0 = v4[4], C1 = v4[5], C2 = v4[6], C3 = v4[7];
        float bc[16] = {B0.x,B0.y,B0.z,B0.w, B1.x,B1.y,B1.z,B1.w,
                        B2.x,B2.y,B2.z,B2.w, B3.x,B3.y,B3.z,B3.w};
        float cc[16] = {C0.x,C0.y,C0.z,C0.w, C1.x,C1.y,C1.z,C1.w,
                        C2.x,C2.y,C2.z,C2.w, C3.x,C3.y,C3.z,C3.w};

        float P[16];
        calc_P(structured, a0, a, dtv, P);

        float acc0 = 0.f, acc1 = 0.f, acc2 = 0.f, acc3 = 0.f;
        #pragma unroll
        for (int s = 0; s < 16; s += 4) {
            h[s+0] = fmaf(P[s+0], h[s+0], du * bc[s+0]);
            h[s+1] = fmaf(P[s+1], h[s+1], du * bc[s+1]);
            h[s+2] = fmaf(P[s+2], h[s+2], du * bc[s+2]);
            h[s+3] = fmaf(P[s+3], h[s+3], du * bc[s+3]);
            acc0 = fmaf(h[s+0], cc[s+0], acc0);
            acc1 = fmaf(h[s+1], cc[s+1], acc1);
            acc2 = fmaf(h[s+2], cc[s+2], acc2);
            acc3 = fmaf(h[s+3], cc[s+3], acc3);
        }
        g_ycat[rb * 1024 + dir * 512 + d] = (acc0 + acc1) + (acc2 + acc3) + u * Dsk;
    }
}

// ---------------------------------------------------------------------------
// LayerNorm over D
// ---------------------------------------------------------------------------
__global__ void ln_kernel(const float* __restrict__ gamma, const float* __restrict__ beta)
{
    __shared__ float r1[256];
    __shared__ float r2[256];
    __shared__ float mu_s, rs_s;
    const int row = blockIdx.x;
    const int tid = threadIdx.x;
    const float* hr = g_hbuf + (size_t)row * D_;
    float v0 = hr[tid], v1 = hr[tid + 256];
    r1[tid] = v0 + v1;
    r2[tid] = v0 * v0 + v1 * v1;
    __syncthreads();
    for (int off = 128; off > 0; off >>= 1) {
        if (tid < off) { r1[tid] += r1[tid + off]; r2[tid] += r2[tid + off]; }
        __syncthreads();
    }
    if (tid == 0) {
        float mu  = r1[0] / (float)D_;
        float var = r2[0] / (float)D_ - mu * mu;
        mu_s = mu;
        rs_s = rsqrtf(var + 1e-5f);
    }
    __syncthreads();
    float mu = mu_s, rs = rs_s;
    g_hn[(size_t)row * D_ + tid]       = (v0 - mu) * rs * gamma[tid]       + beta[tid];
    g_hn[(size_t)row * D_ + tid + 256] = (v1 - mu) * rs * gamma[tid + 256] + beta[tid + 256];
}

// ---------------------------------------------------------------------------
// output transpose + de-normalize
// ---------------------------------------------------------------------------
__global__ void out_kernel(float* __restrict__ out)
{
    int idx = blockIdx.x * 256 + threadIdx.x;
    if (idx >= B_ * PRED_ * N_) return;
    int n = idx % N_;
    int p = (idx / N_) % PRED_;
    int b = idx / (N_ * PRED_);
    float v = g_pre[((size_t)b * T_ + n) * PRED_ + p];
    out[idx] = v * g_std[b * N_ + n] + g_mean[b * N_ + n];
}

// ---------------------------------------------------------------------------
// launch
// ---------------------------------------------------------------------------
extern "C" void kernel_launch(void* const* d_in, const int* in_sizes, int n_in,
                              void* d_out, int out_size)
{
    const float* x_enc  = (const float*)d_in[0];
    const float* x_mark = (const float*)d_in[1];
    const float* W_emb  = (const float*)d_in[4];
    const float* b_emb  = (const float*)d_in[5];
    const float* Alogf  = (const float*)d_in[6];
    const float* Wx_f   = (const float*)d_in[7];
    const float* Wdt_f  = (const float*)d_in[8];
    const float* bdt_f  = (const float*)d_in[9];
    const float* Dsk_f  = (const float*)d_in[10];
    const float* Alogb  = (const float*)d_in[11];
    const float* Wx_b   = (const float*)d_in[12];
    const float* Wdt_b  = (const float*)d_in[13];
    const float* bdt_b  = (const float*)d_in[14];
    const float* Dsk_b  = (const float*)d_in[15];
    const float* Wz     = (const float*)d_in[16];
    const float* bz     = (const float*)d_in[17];
    const float* Wo     = (const float*)d_in[18];
    const float* bo     = (const float*)d_in[19];
    const float* lng    = (const float*)d_in[20];
    const float* lnb    = (const float*)d_in[21];
    const float* Wproj  = (const float*)d_in[22];
    const float* bproj  = (const float*)d_in[23];
    float* out = (float*)d_out;

    float *tok, *enc, *xz, *dtc, *ycat, *fused, *hb, *hn, *pre, *wx, *wdt, *bdt;
    cudaGetSymbolAddress((void**)&tok,   g_tok);
    cudaGetSymbolAddress((void**)&enc,   g_enc);
    cudaGetSymbolAddress((void**)&xz,    g_xz);
    cudaGetSymbolAddress((void**)&dtc,   g_dtcat);
    cudaGetSymbolAddress((void**)&ycat,  g_ycat);
    cudaGetSymbolAddress((void**)&fused, g_fused);
    cudaGetSymbolAddress((void**)&hb,    g_hbuf);
    cudaGetSymbolAddress((void**)&hn,    g_hn);
    cudaGetSymbolAddress((void**)&pre,   g_pre);
    cudaGetSymbolAddress((void**)&wx,    g_wx);
    cudaGetSymbolAddress((void**)&wdt,   g_wdt);
    cudaGetSymbolAddress((void**)&bdt,   g_bdt);

    const int gy = (MROWS + 63) / 64;   // 82

    // 0) pack weights
    pack_kernel<<<512, 256>>>(Wx_f, Wx_b, Wdt_f, Wdt_b, bdt_f, bdt_b);

    // 1) stats
    stats_kernel<<<dim3(B_, (N_ + 31) / 32), 256>>>(x_enc);

    // 2) tok
    build_tok<<<dim3((T_ + 31) / 32, L_ / 32, B_), dim3(32, 8)>>>(x_enc, x_mark);

    // 3) enc = tok @ W_emb + b_emb
    gemm_tc<EPI_NONE><<<dim3(D_ / 128, gy), 256>>>(
        tok, L_, W_emb, D_, enc, D_, MROWS, D_, L_, b_emb, nullptr, nullptr, 0);

    // 4) xz = enc @ [Wx_f|Wx_b]  (one 128-wide GEMM)
    gemm_tc<EPI_NONE><<<dim3(1, gy), 256>>>(
        enc, D_, wx, 128, xz, 128, MROWS, 128, D_, nullptr, nullptr, nullptr, 0);

    // 5) dtcat = softplus(xz @ Wdt_blockdiag + bdt_cat)
    gemm_tc<EPI_SOFTPLUS><<<dim3(1024 / 128, gy), 256>>>(
        xz, 128, wdt, 1024, dtc, 1024, MROWS, 1024, 128, bdt, nullptr, nullptr, 0);

    // 6) chunked bidirectional scan -> g_ycat
    scan_partial<<<dim3(4 * NC_, B_, 2), 128>>>(Alogf, Alogb);
    scan_combine<<<64, 256>>>(Alogf, Alogb);
    scan_final  <<<dim3(4 * NC_, B_, 2), 128>>>(Alogf, Alogb, Dsk_f, Dsk_b);

    // 7) fused = sigmoid(ycat @ Wz + bz) gating of yf/yb
    gemm_tc<EPI_SIGFUSE><<<dim3(D_ / 128, gy), 256>>>(
        ycat, 2 * D_, Wz, D_, fused, D_, MROWS, D_, 2 * D_, bz,
        ycat, ycat + D_, 2 * D_);

    // 8) h = enc + fused @ Wo + bo
    gemm_tc<EPI_ADD><<<dim3(D_ / 128, gy), 256>>>(
        fused, D_, Wo, D_, hb, D_, MROWS, D_, D_, bo, enc, nullptr, D_);

    // 9) layernorm
    ln_kernel<<<MROWS, 256>>>(lng, lnb);

    // 10) pre = hn @ W_proj + b_proj
    gemm_tc<EPI_NONE><<<dim3(1, gy), 256>>>(
        hn, D_, Wproj, PRED_, pre, PRED_, MROWS, PRED_, D_, bproj, nullptr, nullptr, 0);

    // 11) output
    out_kernel<<<(B_ * PRED_ * N_ + 255) / 256, 256>>>(out);
}